// round 7
// baseline (speedup 1.0000x reference)
#include <cuda_runtime.h>
#include <cuda_fp16.h>
#include <mma.h>
#include <cstdint>
#include <math.h>

using namespace nvcuda;

// x: (8,4096,512) f32 ; w_qkv: (1536,512) ; w_proj: (512,512) ; b_proj: (512)
// H=8, head_dim=64, W=64, SHIFT=32, SCALE=0.125
#define NTOK (8 * 4096)

// -------- scratch (__device__ globals; no allocation allowed) --------
__device__ __half g_x16[(size_t)NTOK * 512];     // rolled(-32) x, fp16
__device__ __half g_qkv16[(size_t)NTOK * 1536];  // q|k|v per token, fp16
__device__ __half g_att16[(size_t)NTOK * 512];   // scrambled attention out, fp16
__device__ __half g_wqkv16[1536 * 512];
__device__ __half g_wproj16[512 * 512];

// ---------------------------------------------------------------------------
// cp.async helpers
// ---------------------------------------------------------------------------
__device__ __forceinline__ void cp_async16(void* smem_dst, const void* gmem_src) {
    unsigned sa = (unsigned)__cvta_generic_to_shared(smem_dst);
    asm volatile("cp.async.cg.shared.global [%0], [%1], 16;" :: "r"(sa), "l"(gmem_src));
}
__device__ __forceinline__ void cp_async_commit() {
    asm volatile("cp.async.commit_group;");
}
__device__ __forceinline__ void cp_async_wait1() {
    asm volatile("cp.async.wait_group 1;");
}

// ---------------------------------------------------------------------------
// conversion kernels (fp32 -> fp16), roll(-32) fused into x conversion
// ---------------------------------------------------------------------------
__global__ void conv_x_kernel(const float* __restrict__ x) {
    size_t idx = (size_t)blockIdx.x * 256 + threadIdx.x; // one float4 each
    int m = (int)(idx >> 7);
    int c = (int)(idx & 127) * 4;
    int msrc = (m & ~4095) | (((m & 4095) + 32) & 4095); // roll(-32)
    float4 v = *(const float4*)(x + (size_t)msrc * 512 + c);
    __half2 h0 = __floats2half2_rn(v.x, v.y);
    __half2 h1 = __floats2half2_rn(v.z, v.w);
    uint2 u;
    u.x = *(const unsigned*)&h0;
    u.y = *(const unsigned*)&h1;
    *(uint2*)(g_x16 + (size_t)m * 512 + c) = u;
}

__global__ void conv_w_kernel(const float* __restrict__ src, __half* __restrict__ dst, int n4) {
    int idx = blockIdx.x * 256 + threadIdx.x;
    if (idx >= n4) return;
    float4 v = *(const float4*)(src + (size_t)idx * 4);
    __half2 h0 = __floats2half2_rn(v.x, v.y);
    __half2 h1 = __floats2half2_rn(v.z, v.w);
    uint2 u;
    u.x = *(const unsigned*)&h0;
    u.y = *(const unsigned*)&h1;
    *(uint2*)(dst + (size_t)idx * 4) = u;
}

// ---------------------------------------------------------------------------
// Tensor-core GEMM, 3-stage cp.async ring: C[m,n] = sum_k A[m,k]*B[n,k], K=512
// A: Mx512 fp16 row-major. B: Nx512 fp16 row-major (= col-major matrix_b).
// MODE 0: A=g_x16,  B=g_wqkv16,  C=g_qkv16 (fp16, ldc 1536), no bias
// MODE 1: A=g_att16, B=g_wproj16, C=d_out fp32 (ldc 512), + bias, + roll(+32)
// BM=128, BN=256, BK=32, 8 warps (2M x 4N), warp tile 64x64 (rA=rB=4).
// Dynamic smem: 3 stages * (128+256) rows * 40 halves * 2B = 92160 B.
// ---------------------------------------------------------------------------
template <int MODE>
__global__ __launch_bounds__(256) void gemm_wmma(const __half* __restrict__ Aglob,
                                                 const __half* __restrict__ Bglob,
                                                 const float* __restrict__ bias,
                                                 float* __restrict__ Cout)
{
    constexpr int BK = 32;
    constexpr int LDS = BK + 8;      // 40 halves
    constexpr int A_STG = 128 * LDS; // halves
    constexpr int B_STG = 256 * LDS;
    extern __shared__ __align__(16) uint8_t smem_raw[];
    __half* smem_h = (__half*)smem_raw;

    // layout: [A s0][A s1][A s2][B s0][B s1][B s2]
    auto sA = [&](int s, int r, int c) -> __half* { return smem_h + s * A_STG + r * LDS + c; };
    auto sB = [&](int s, int r, int c) -> __half* {
        return smem_h + 3 * A_STG + s * B_STG + r * LDS + c;
    };

    const int tid = threadIdx.x;
    const int wid = tid >> 5;
    const int lane = tid & 31;
    const int warpM = wid >> 2; // 0..1 -> 64-row slab
    const int warpN = wid & 3;  // 0..3 -> 64-col slab
    const int m0 = blockIdx.y * 128;
    const int n0 = blockIdx.x * 256;

    wmma::fragment<wmma::accumulator, 16, 16, 16, float> acc[4][4];

    if (MODE == 1) {
        // stage row-broadcast bias, load into accumulators (layout-agnostic)
        float (*sBias)[264] = (float (*)[264])smem_raw;
        {
            float bv = bias[n0 + tid];
#pragma unroll
            for (int r = 0; r < 16; ++r) sBias[r][tid] = bv;
        }
        __syncthreads();
#pragma unroll
        for (int i = 0; i < 4; ++i)
#pragma unroll
            for (int j = 0; j < 4; ++j)
                wmma::load_matrix_sync(acc[i][j], &sBias[0][warpN * 64 + j * 16], 264,
                                       wmma::mem_row_major);
        __syncthreads();
    } else {
#pragma unroll
        for (int i = 0; i < 4; ++i)
#pragma unroll
            for (int j = 0; j < 4; ++j) wmma::fill_fragment(acc[i][j], 0.0f);
    }

    // cp.async mapping: 4 threads per row (1 uint4 = 8 halves), 64 rows/pass.
    // A: 2 passes (128 rows); B: 4 passes (256 rows). 6 cp.async per thread.
    const int lr = tid >> 2;
    const int lc = (tid & 3) * 8;

    auto load_stage = [&](int s, int kt) {
        const int k0 = kt * BK;
#pragma unroll
        for (int p = 0; p < 2; ++p) {
            int row = p * 64 + lr;
            cp_async16(sA(s, row, lc), Aglob + (size_t)(m0 + row) * 512 + k0 + lc);
        }
#pragma unroll
        for (int p = 0; p < 4; ++p) {
            int row = p * 64 + lr;
            cp_async16(sB(s, row, lc), Bglob + (size_t)(n0 + row) * 512 + k0 + lc);
        }
    };

    load_stage(0, 0);
    cp_async_commit();
    load_stage(1, 1);
    cp_async_commit();

    for (int kt = 0; kt < 16; ++kt) {
        cp_async_wait1();
        __syncthreads();

        if (kt + 2 < 16) load_stage((kt + 2) % 3, kt + 2);
        cp_async_commit();

        const int s = kt % 3;
#pragma unroll
        for (int ks = 0; ks < BK; ks += 16) {
            wmma::fragment<wmma::matrix_a, 16, 16, 16, __half, wmma::row_major> af[4];
            wmma::fragment<wmma::matrix_b, 16, 16, 16, __half, wmma::col_major> bf[4];
#pragma unroll
            for (int i = 0; i < 4; ++i)
                wmma::load_matrix_sync(af[i], sA(s, warpM * 64 + i * 16, ks), LDS);
#pragma unroll
            for (int j = 0; j < 4; ++j)
                wmma::load_matrix_sync(bf[j], sB(s, warpN * 64 + j * 16, ks), LDS);
#pragma unroll
            for (int i = 0; i < 4; ++i)
#pragma unroll
                for (int j = 0; j < 4; ++j)
                    wmma::mma_sync(acc[i][j], af[i], bf[j], acc[i][j]);
        }
    }
    __syncthreads(); // smem reuse below

    if (MODE == 0) {
        // fp16 epilogue: per-warp 64x64 fp32 staging in smem, 2 rounds of 4 warps
        float* stg = (float*)smem_raw + (size_t)warpN * 4096; // 16 KB per warp
        const int rrow = lane >> 3;      // 0..3
        const int ccol = (lane & 7) * 8; // 0..56
#pragma unroll
        for (int round = 0; round < 2; ++round) {
            if (warpM == round) {
#pragma unroll
                for (int i = 0; i < 4; ++i)
#pragma unroll
                    for (int j = 0; j < 4; ++j)
                        wmma::store_matrix_sync(stg + i * 16 * 64 + j * 16, acc[i][j], 64,
                                                wmma::mem_row_major);
                __syncwarp();
#pragma unroll
                for (int p = 0; p < 16; ++p) {
                    int row = p * 4 + rrow;
                    const float* sp = stg + row * 64 + ccol;
                    __half* gp = g_qkv16 + (size_t)(m0 + warpM * 64 + row) * 1536 +
                                 n0 + warpN * 64 + ccol;
                    float4 a = *(const float4*)(sp);
                    float4 b = *(const float4*)(sp + 4);
                    __half2 h0 = __floats2half2_rn(a.x, a.y);
                    __half2 h1 = __floats2half2_rn(a.z, a.w);
                    __half2 h2 = __floats2half2_rn(b.x, b.y);
                    __half2 h3 = __floats2half2_rn(b.z, b.w);
                    uint4 u;
                    u.x = *(unsigned*)&h0;
                    u.y = *(unsigned*)&h1;
                    u.z = *(unsigned*)&h2;
                    u.w = *(unsigned*)&h3;
                    *(uint4*)gp = u;
                }
            }
            __syncthreads();
        }
    } else {
        // fp32 direct store with roll(+32) (16-row frags stay contiguous)
#pragma unroll
        for (int i = 0; i < 4; ++i) {
            int m = m0 + warpM * 64 + i * 16;
            int r = (m & 4095) + 32;
            if (r >= 4096) r -= 4096;
            int mo = (m & ~4095) | r;
            float* cp = Cout + (size_t)mo * 512 + n0 + warpN * 64;
#pragma unroll
            for (int j = 0; j < 4; ++j)
                wmma::store_matrix_sync(cp + j * 16, acc[i][j], 512, wmma::mem_row_major);
        }
    }
}

// ---------------------------------------------------------------------------
// Per-token 8x8 head-mixing attention + output scramble (fp32 math).
// K/V staged fp16 in smem, converted on use.
//   S[h,g] = 0.125 * q[h]·k[g];  P = softmax_g(S);  o[h] = P·v
//   g_att16[b, wi*64 + h*8 + w/8, (w%8)*64 + d] = o[h,d]
// ---------------------------------------------------------------------------
__global__ __launch_bounds__(128) void attn_kernel()
{
    __shared__ __half kv[16][1040]; // [token][ k(512) | v(512) ] fp16, padded

    const int tid = threadIdx.x;
    const int tok0 = blockIdx.x * 16;

    for (int i = tid; i < 16 * 128; i += 128) {
        int t = i >> 7;
        int off = i & 127;
        uint4 u = *(const uint4*)(g_qkv16 + (size_t)(tok0 + t) * 1536 + 512 + off * 8);
        *(uint4*)(&kv[t][off * 8]) = u;
    }
    __syncthreads();

    const int lt = tid >> 3;
    const int h = tid & 7;
    const int tok = tok0 + lt;

    const __half* qp = g_qkv16 + (size_t)tok * 1536 + h * 64;

    float S[8];
#pragma unroll
    for (int g = 0; g < 8; g++) S[g] = 0.f;

#pragma unroll
    for (int d0 = 0; d0 < 64; d0 += 8) {
        uint4 u = *(const uint4*)(qp + d0);
        const __half2* hp = (const __half2*)&u;
        float qf[8];
#pragma unroll
        for (int j = 0; j < 4; ++j) {
            float2 f = __half22float2(hp[j]);
            qf[j * 2 + 0] = f.x;
            qf[j * 2 + 1] = f.y;
        }
#pragma unroll
        for (int g = 0; g < 8; g++) {
            const __half2* kr = (const __half2*)&kv[lt][g * 64 + d0];
            float s = 0.f;
#pragma unroll
            for (int j = 0; j < 4; ++j) {
                float2 f = __half22float2(kr[j]);
                s += qf[j * 2] * f.x + qf[j * 2 + 1] * f.y;
            }
            S[g] += s;
        }
    }

    float mx = -INFINITY;
#pragma unroll
    for (int g = 0; g < 8; g++) {
        S[g] *= 0.125f;
        mx = fmaxf(mx, S[g]);
    }
    float sum = 0.f;
#pragma unroll
    for (int g = 0; g < 8; g++) {
        S[g] = expf(S[g] - mx);
        sum += S[g];
    }
    float inv = 1.f / sum;
#pragma unroll
    for (int g = 0; g < 8; g++) S[g] *= inv;

    const int n = tok & 4095;
    const int wi = n >> 6;
    const int w = n & 63;
    const int n2 = (wi << 6) | (h << 3) | (w >> 3);
    __half* op = g_att16 + (size_t)((tok & ~4095) | n2) * 512 + ((w & 7) << 6);

#pragma unroll
    for (int d0 = 0; d0 < 64; d0 += 4) {
        float4 o4 = {0.f, 0.f, 0.f, 0.f};
#pragma unroll
        for (int g = 0; g < 8; g++) {
            const __half2* vr = (const __half2*)&kv[lt][512 + g * 64 + d0];
            float2 f0 = __half22float2(vr[0]);
            float2 f1 = __half22float2(vr[1]);
            o4.x += S[g] * f0.x;
            o4.y += S[g] * f0.y;
            o4.z += S[g] * f1.x;
            o4.w += S[g] * f1.y;
        }
        __half2 h0 = __floats2half2_rn(o4.x, o4.y);
        __half2 h1 = __floats2half2_rn(o4.z, o4.w);
        uint2 u;
        u.x = *(const unsigned*)&h0;
        u.y = *(const unsigned*)&h1;
        *(uint2*)(op + d0) = u;
    }
}

// ---------------------------------------------------------------------------
extern "C" void kernel_launch(void* const* d_in, const int* in_sizes, int n_in,
                              void* d_out, int out_size)
{
    const float* x = (const float*)d_in[0];
    const float* w_qkv = (const float*)d_in[1];
    const float* w_proj = (const float*)d_in[2];
    const float* b_proj = (const float*)d_in[3];
    float* out = (float*)d_out;
    (void)in_sizes; (void)n_in; (void)out_size;

    __half* wq16;
    __half* wp16;
    __half* x16;
    __half* a16;
    cudaGetSymbolAddress((void**)&wq16, g_wqkv16);
    cudaGetSymbolAddress((void**)&wp16, g_wproj16);
    cudaGetSymbolAddress((void**)&x16, g_x16);
    cudaGetSymbolAddress((void**)&a16, g_att16);

    constexpr int GEMM_SMEM = 3 * (128 + 256) * 40 * 2; // 92160 B
    cudaFuncSetAttribute(gemm_wmma<0>, cudaFuncAttributeMaxDynamicSharedMemorySize, GEMM_SMEM);
    cudaFuncSetAttribute(gemm_wmma<1>, cudaFuncAttributeMaxDynamicSharedMemorySize, GEMM_SMEM);

    // 1) fp16 conversions (roll(-32) fused into x)
    conv_x_kernel<<<(NTOK * 512 / 4) / 256, 256>>>(x);
    conv_w_kernel<<<(1536 * 512 / 4 + 255) / 256, 256>>>(w_qkv, wq16, 1536 * 512 / 4);
    conv_w_kernel<<<(512 * 512 / 4 + 255) / 256, 256>>>(w_proj, wp16, 512 * 512 / 4);

    // 2) QKV GEMM (tensor cores, 64x64 warp tiles) -> g_qkv16 fp16
    gemm_wmma<0><<<dim3(1536 / 256, NTOK / 128), 256, GEMM_SMEM>>>(x16, wq16, nullptr, nullptr);

    // 3) per-token 8x8 head attention + scramble -> g_att16
    attn_kernel<<<NTOK / 16, 128>>>();

    // 4) proj GEMM + bias + roll(+32) -> d_out
    gemm_wmma<1><<<dim3(512 / 256, NTOK / 128), 256, GEMM_SMEM>>>(a16, wp16, b_proj, out);
}

// round 8
// speedup vs baseline: 1.2317x; 1.2317x over previous
#include <cuda_runtime.h>
#include <cuda_fp16.h>
#include <cstdint>
#include <math.h>

// x: (8,4096,512) f32 ; w_qkv: (1536,512) ; w_proj: (512,512) ; b_proj: (512)
// H=8, head_dim=64, W=64, SHIFT=32, SCALE=0.125
#define NTOK (8 * 4096)

// -------- scratch (__device__ globals; no allocation allowed) --------
__device__ __half g_x16[(size_t)NTOK * 512];     // rolled(-32) x, fp16
__device__ __half g_qkv16[(size_t)NTOK * 1536];  // q|k|v per token, fp16
__device__ __half g_att16[(size_t)NTOK * 512];   // scrambled attention out, fp16
__device__ __half g_wqkv16[1536 * 512];
__device__ __half g_wproj16[512 * 512];

// ---------------------------------------------------------------------------
// PTX helpers
// ---------------------------------------------------------------------------
__device__ __forceinline__ void cp16(uint32_t smem_addr, const void* gmem_src) {
    asm volatile("cp.async.cg.shared.global [%0], [%1], 16;" :: "r"(smem_addr), "l"(gmem_src));
}
__device__ __forceinline__ void cp_commit() { asm volatile("cp.async.commit_group;"); }
__device__ __forceinline__ void cp_wait1() { asm volatile("cp.async.wait_group 1;"); }

#define LDSM_X4(R0, R1, R2, R3, ADDR)                                             \
    asm volatile("ldmatrix.sync.aligned.m8n8.x4.shared.b16 {%0,%1,%2,%3}, [%4];"  \
                 : "=r"(R0), "=r"(R1), "=r"(R2), "=r"(R3) : "r"(ADDR))

__device__ __forceinline__ void mma16816(float* c, const uint32_t* a, uint32_t b0, uint32_t b1) {
    asm volatile(
        "mma.sync.aligned.m16n8k16.row.col.f32.f16.f16.f32 "
        "{%0,%1,%2,%3}, {%4,%5,%6,%7}, {%8,%9}, {%0,%1,%2,%3};"
        : "+f"(c[0]), "+f"(c[1]), "+f"(c[2]), "+f"(c[3])
        : "r"(a[0]), "r"(a[1]), "r"(a[2]), "r"(a[3]), "r"(b0), "r"(b1));
}

// ---------------------------------------------------------------------------
// conversion kernels (fp32 -> fp16), roll(-32) fused into x conversion
// ---------------------------------------------------------------------------
__global__ void conv_x_kernel(const float* __restrict__ x) {
    size_t idx = (size_t)blockIdx.x * 256 + threadIdx.x; // one float4 each
    int m = (int)(idx >> 7);
    int c = (int)(idx & 127) * 4;
    int msrc = (m & ~4095) | (((m & 4095) + 32) & 4095); // roll(-32)
    float4 v = *(const float4*)(x + (size_t)msrc * 512 + c);
    __half2 h0 = __floats2half2_rn(v.x, v.y);
    __half2 h1 = __floats2half2_rn(v.z, v.w);
    uint2 u;
    u.x = *(const unsigned*)&h0;
    u.y = *(const unsigned*)&h1;
    *(uint2*)(g_x16 + (size_t)m * 512 + c) = u;
}

__global__ void conv_w_kernel(const float* __restrict__ src, __half* __restrict__ dst, int n4) {
    int idx = blockIdx.x * 256 + threadIdx.x;
    if (idx >= n4) return;
    float4 v = *(const float4*)(src + (size_t)idx * 4);
    __half2 h0 = __floats2half2_rn(v.x, v.y);
    __half2 h1 = __floats2half2_rn(v.z, v.w);
    uint2 u;
    u.x = *(const unsigned*)&h0;
    u.y = *(const unsigned*)&h1;
    *(uint2*)(dst + (size_t)idx * 4) = u;
}

// ---------------------------------------------------------------------------
// mma.sync GEMM: C[m,n] = sum_k A[m,k]*B[n,k], K=512.
// A: Mx512 fp16 row-major; B: Nx512 fp16 row-major (TN -> mma row.col).
// MODE 0: A=g_x16,  B=g_wqkv16,  C=g_qkv16 (fp16, ldc 1536), no bias
// MODE 1: A=g_att16, B=g_wproj16, C=d_out fp32 (ldc 512), + bias, + roll(+32)
// BM=128, BN=256, BK=64 (rows = 128B, XOR swizzle ch^=row&7), 3-stage cp.async.
// 8 warps (2M x 4N), warp tile 64x64 = 4 m-frags x 8 n-frags (m16n8k16).
// Dynamic smem: 3*(128+256)*128B = 147456 B.
// ---------------------------------------------------------------------------
template <int MODE>
__global__ __launch_bounds__(256) void gemm_mma(const __half* __restrict__ Aglob,
                                                const __half* __restrict__ Bglob,
                                                const float* __restrict__ bias,
                                                float* __restrict__ Cout)
{
    constexpr int ASTG = 128 * 128; // bytes per A stage
    constexpr int BSTG = 256 * 128; // bytes per B stage
    extern __shared__ __align__(16) uint8_t smem_raw[];
    const uint32_t sbase = (uint32_t)__cvta_generic_to_shared(smem_raw);

    const int tid = threadIdx.x;
    const int wid = tid >> 5;
    const int lane = tid & 31;
    const int warpM = wid >> 2; // 0..1 -> 64-row slab
    const int warpN = wid & 3;  // 0..3 -> 64-col slab
    const int m0 = blockIdx.y * 128;
    const int n0 = blockIdx.x * 256;

    float acc[4][8][4];
#pragma unroll
    for (int i = 0; i < 4; ++i)
#pragma unroll
        for (int j = 0; j < 8; ++j)
#pragma unroll
            for (int r = 0; r < 4; ++r) acc[i][j][r] = 0.f;

    // ldmatrix per-lane geometry
    const int amat = lane >> 3;      // 0..3
    const int amrow = lane & 7;      // row within 8x8 mat
    const int rA_loc = (amat & 1) * 8 + amrow; // row within 16-row frag
    const int chA = amat >> 1;                 // k-chunk selector (0/1)
    const int nB_loc = (lane >> 4) * 8 + (lane & 7); // row within 16-col (n) pair
    const int chB = (lane >> 3) & 1;                 // k-chunk selector

    // cp.async mapping: idx -> (row, 16B chunk); swizzle chunk ^= row&7
    auto load_stage = [&](int s, int kt) {
        const int k0 = kt * 64; // halves
        const uint32_t aB = sbase + s * ASTG;
        const uint32_t bB = sbase + 3 * ASTG + s * BSTG;
#pragma unroll
        for (int it = 0; it < 4; ++it) { // A: 128 rows x 8 chunks = 1024
            int idx = it * 256 + tid;
            int r = idx >> 3, ch = idx & 7;
            cp16(aB + r * 128 + ((ch ^ (r & 7)) << 4),
                 Aglob + (size_t)(m0 + r) * 512 + k0 + ch * 8);
        }
#pragma unroll
        for (int it = 0; it < 8; ++it) { // B: 256 rows x 8 chunks = 2048
            int idx = it * 256 + tid;
            int r = idx >> 3, ch = idx & 7;
            cp16(bB + r * 128 + ((ch ^ (r & 7)) << 4),
                 Bglob + (size_t)(n0 + r) * 512 + k0 + ch * 8);
        }
    };

    load_stage(0, 0);
    cp_commit();
    load_stage(1, 1);
    cp_commit();

    for (int kt = 0; kt < 8; ++kt) {
        cp_wait1();
        __syncthreads();

        if (kt + 2 < 8) load_stage((kt + 2) % 3, kt + 2);
        cp_commit();

        const int s = kt % 3;
        const uint32_t aB = sbase + s * ASTG;
        const uint32_t bB = sbase + 3 * ASTG + s * BSTG;

#pragma unroll
        for (int kc = 0; kc < 4; ++kc) { // 4 x k16 within BK=64
            uint32_t a[4][4];
#pragma unroll
            for (int i = 0; i < 4; ++i) {
                int r = warpM * 64 + i * 16 + rA_loc;
                uint32_t addr = aB + r * 128 + ((((kc << 1) + chA) ^ (r & 7)) << 4);
                LDSM_X4(a[i][0], a[i][1], a[i][2], a[i][3], addr);
            }
#pragma unroll
            for (int j2 = 0; j2 < 4; ++j2) { // n16 pair -> two n8 frags
                uint32_t b0, b1, b2, b3;
                int n = warpN * 64 + j2 * 16 + nB_loc;
                uint32_t addr = bB + n * 128 + ((((kc << 1) + chB) ^ (n & 7)) << 4);
                LDSM_X4(b0, b1, b2, b3, addr);
#pragma unroll
                for (int i = 0; i < 4; ++i) {
                    mma16816(acc[i][j2 * 2 + 0], a[i], b0, b1);
                    mma16816(acc[i][j2 * 2 + 1], a[i], b2, b3);
                }
            }
        }
    }

    // ---- epilogue (register layout: c0,c1 -> row lane/4, cols 2*(lane%4);
    //                c2,c3 -> row+8, same cols) ----
    const int trow = lane >> 2;
    const int tcol = (lane & 3) * 2;

    if (MODE == 0) {
#pragma unroll
        for (int i = 0; i < 4; ++i) {
            int r0 = m0 + warpM * 64 + i * 16 + trow;
            __half* p0 = g_qkv16 + (size_t)r0 * 1536 + n0 + warpN * 64 + tcol;
            __half* p1 = p0 + 8 * 1536;
#pragma unroll
            for (int j = 0; j < 8; ++j) {
                __half2 h0 = __floats2half2_rn(acc[i][j][0], acc[i][j][1]);
                __half2 h1 = __floats2half2_rn(acc[i][j][2], acc[i][j][3]);
                *(__half2*)(p0 + j * 8) = h0;
                *(__half2*)(p1 + j * 8) = h1;
            }
        }
    } else {
        const int col = n0 + warpN * 64 + tcol;
#pragma unroll
        for (int i = 0; i < 4; ++i) {
            int m = m0 + warpM * 64 + i * 16 + trow;
            int r = (m & 4095) + 32;
            if (r >= 4096) r -= 4096;
            int mo0 = (m & ~4095) | r;
            int r2 = ((m + 8) & 4095) + 32;
            if (r2 >= 4096) r2 -= 4096;
            int mo1 = ((m + 8) & ~4095) | r2;
            float* p0 = Cout + (size_t)mo0 * 512 + col;
            float* p1 = Cout + (size_t)mo1 * 512 + col;
#pragma unroll
            for (int j = 0; j < 8; ++j) {
                float2 bv = *(const float2*)(bias + col + j * 8);
                float2 v0 = {acc[i][j][0] + bv.x, acc[i][j][1] + bv.y};
                float2 v1 = {acc[i][j][2] + bv.x, acc[i][j][3] + bv.y};
                *(float2*)(p0 + j * 8) = v0;
                *(float2*)(p1 + j * 8) = v1;
            }
        }
    }
}

// ---------------------------------------------------------------------------
// Per-token 8x8 head-mixing attention + output scramble (fp32 math).
// K/V staged fp16 in smem, converted on use.
//   S[h,g] = 0.125 * q[h]·k[g];  P = softmax_g(S);  o[h] = P·v
//   g_att16[b, wi*64 + h*8 + w/8, (w%8)*64 + d] = o[h,d]
// ---------------------------------------------------------------------------
__global__ __launch_bounds__(128) void attn_kernel()
{
    __shared__ __half kv[16][1040]; // [token][ k(512) | v(512) ] fp16, padded

    const int tid = threadIdx.x;
    const int tok0 = blockIdx.x * 16;

    for (int i = tid; i < 16 * 128; i += 128) {
        int t = i >> 7;
        int off = i & 127;
        uint4 u = *(const uint4*)(g_qkv16 + (size_t)(tok0 + t) * 1536 + 512 + off * 8);
        *(uint4*)(&kv[t][off * 8]) = u;
    }
    __syncthreads();

    const int lt = tid >> 3;
    const int h = tid & 7;
    const int tok = tok0 + lt;

    const __half* qp = g_qkv16 + (size_t)tok * 1536 + h * 64;

    float S[8];
#pragma unroll
    for (int g = 0; g < 8; g++) S[g] = 0.f;

#pragma unroll
    for (int d0 = 0; d0 < 64; d0 += 8) {
        uint4 u = *(const uint4*)(qp + d0);
        const __half2* hp = (const __half2*)&u;
        float qf[8];
#pragma unroll
        for (int j = 0; j < 4; ++j) {
            float2 f = __half22float2(hp[j]);
            qf[j * 2 + 0] = f.x;
            qf[j * 2 + 1] = f.y;
        }
#pragma unroll
        for (int g = 0; g < 8; g++) {
            const __half2* kr = (const __half2*)&kv[lt][g * 64 + d0];
            float s = 0.f;
#pragma unroll
            for (int j = 0; j < 4; ++j) {
                float2 f = __half22float2(kr[j]);
                s += qf[j * 2] * f.x + qf[j * 2 + 1] * f.y;
            }
            S[g] += s;
        }
    }

    float mx = -INFINITY;
#pragma unroll
    for (int g = 0; g < 8; g++) {
        S[g] *= 0.125f;
        mx = fmaxf(mx, S[g]);
    }
    float sum = 0.f;
#pragma unroll
    for (int g = 0; g < 8; g++) {
        S[g] = expf(S[g] - mx);
        sum += S[g];
    }
    float inv = 1.f / sum;
#pragma unroll
    for (int g = 0; g < 8; g++) S[g] *= inv;

    const int n = tok & 4095;
    const int wi = n >> 6;
    const int w = n & 63;
    const int n2 = (wi << 6) | (h << 3) | (w >> 3);
    __half* op = g_att16 + (size_t)((tok & ~4095) | n2) * 512 + ((w & 7) << 6);

#pragma unroll
    for (int d0 = 0; d0 < 64; d0 += 4) {
        float4 o4 = {0.f, 0.f, 0.f, 0.f};
#pragma unroll
        for (int g = 0; g < 8; g++) {
            const __half2* vr = (const __half2*)&kv[lt][512 + g * 64 + d0];
            float2 f0 = __half22float2(vr[0]);
            float2 f1 = __half22float2(vr[1]);
            o4.x += S[g] * f0.x;
            o4.y += S[g] * f0.y;
            o4.z += S[g] * f1.x;
            o4.w += S[g] * f1.y;
        }
        __half2 h0 = __floats2half2_rn(o4.x, o4.y);
        __half2 h1 = __floats2half2_rn(o4.z, o4.w);
        uint2 u;
        u.x = *(const unsigned*)&h0;
        u.y = *(const unsigned*)&h1;
        *(uint2*)(op + d0) = u;
    }
}

// ---------------------------------------------------------------------------
extern "C" void kernel_launch(void* const* d_in, const int* in_sizes, int n_in,
                              void* d_out, int out_size)
{
    const float* x = (const float*)d_in[0];
    const float* w_qkv = (const float*)d_in[1];
    const float* w_proj = (const float*)d_in[2];
    const float* b_proj = (const float*)d_in[3];
    float* out = (float*)d_out;
    (void)in_sizes; (void)n_in; (void)out_size;

    __half* wq16;
    __half* wp16;
    __half* x16;
    __half* a16;
    cudaGetSymbolAddress((void**)&wq16, g_wqkv16);
    cudaGetSymbolAddress((void**)&wp16, g_wproj16);
    cudaGetSymbolAddress((void**)&x16, g_x16);
    cudaGetSymbolAddress((void**)&a16, g_att16);

    constexpr int GEMM_SMEM = 3 * (128 + 256) * 128; // 147456 B
    cudaFuncSetAttribute(gemm_mma<0>, cudaFuncAttributeMaxDynamicSharedMemorySize, GEMM_SMEM);
    cudaFuncSetAttribute(gemm_mma<1>, cudaFuncAttributeMaxDynamicSharedMemorySize, GEMM_SMEM);

    // 1) fp16 conversions (roll(-32) fused into x)
    conv_x_kernel<<<(NTOK * 512 / 4) / 256, 256>>>(x);
    conv_w_kernel<<<(1536 * 512 / 4 + 255) / 256, 256>>>(w_qkv, wq16, 1536 * 512 / 4);
    conv_w_kernel<<<(512 * 512 / 4 + 255) / 256, 256>>>(w_proj, wp16, 512 * 512 / 4);

    // 2) QKV GEMM (mma.sync + ldmatrix, swizzled) -> g_qkv16 fp16
    gemm_mma<0><<<dim3(1536 / 256, NTOK / 128), 256, GEMM_SMEM>>>(x16, wq16, nullptr, nullptr);

    // 3) per-token 8x8 head attention + scramble -> g_att16
    attn_kernel<<<NTOK / 16, 128>>>();

    // 4) proj GEMM + bias + roll(+32) -> d_out
    gemm_mma<1><<<dim3(512 / 256, NTOK / 128), 256, GEMM_SMEM>>>(a16, wp16, b_proj, out);
}

// round 13
// speedup vs baseline: 1.3680x; 1.1107x over previous
#include <cuda_runtime.h>
#include <cuda_fp16.h>
#include <cstdint>
#include <math.h>

// x: (8,4096,512) f32 ; w_qkv: (1536,512) ; w_proj: (512,512) ; b_proj: (512)
// H=8, head_dim=64, W=64, SHIFT=32, SCALE=0.125
#define NTOK (8 * 4096)

// -------- scratch (__device__ globals; no allocation allowed) --------
__device__ __half g_x16[(size_t)NTOK * 512];     // rolled(-32) x, fp16
__device__ __half g_qkv16[(size_t)NTOK * 1536];  // q|k|v per token, fp16
__device__ __half g_att16[(size_t)NTOK * 512];   // scrambled attention out, fp16
__device__ __half g_wqkv16[1536 * 512];
__device__ __half g_wproj16[512 * 512];

// ---------------------------------------------------------------------------
// PTX helpers
// ---------------------------------------------------------------------------
__device__ __forceinline__ void cp16(uint32_t smem_addr, const void* gmem_src) {
    asm volatile("cp.async.cg.shared.global [%0], [%1], 16;" :: "r"(smem_addr), "l"(gmem_src));
}
__device__ __forceinline__ void cp_commit() { asm volatile("cp.async.commit_group;"); }
__device__ __forceinline__ void cp_wait1() { asm volatile("cp.async.wait_group 1;"); }

#define LDSM_X4(R0, R1, R2, R3, ADDR)                                             \
    asm volatile("ldmatrix.sync.aligned.m8n8.x4.shared.b16 {%0,%1,%2,%3}, [%4];"  \
                 : "=r"(R0), "=r"(R1), "=r"(R2), "=r"(R3) : "r"(ADDR))

__device__ __forceinline__ void mma16816(float* c, const uint32_t* a, uint32_t b0, uint32_t b1) {
    asm volatile(
        "mma.sync.aligned.m16n8k16.row.col.f32.f16.f16.f32 "
        "{%0,%1,%2,%3}, {%4,%5,%6,%7}, {%8,%9}, {%0,%1,%2,%3};"
        : "+f"(c[0]), "+f"(c[1]), "+f"(c[2]), "+f"(c[3])
        : "r"(a[0]), "r"(a[1]), "r"(a[2]), "r"(a[3]), "r"(b0), "r"(b1));
}

// ---------------------------------------------------------------------------
// conversion kernels (fp32 -> fp16), roll(-32) fused into x conversion
// ---------------------------------------------------------------------------
__global__ void conv_x_kernel(const float* __restrict__ x) {
    size_t idx = (size_t)blockIdx.x * 256 + threadIdx.x; // one float4 each
    int m = (int)(idx >> 7);
    int c = (int)(idx & 127) * 4;
    int msrc = (m & ~4095) | (((m & 4095) + 32) & 4095); // roll(-32)
    float4 v = *(const float4*)(x + (size_t)msrc * 512 + c);
    __half2 h0 = __floats2half2_rn(v.x, v.y);
    __half2 h1 = __floats2half2_rn(v.z, v.w);
    uint2 u;
    u.x = *(const unsigned*)&h0;
    u.y = *(const unsigned*)&h1;
    *(uint2*)(g_x16 + (size_t)m * 512 + c) = u;
}

__global__ void conv_w_kernel(const float* __restrict__ src, __half* __restrict__ dst, int n4) {
    int idx = blockIdx.x * 256 + threadIdx.x;
    if (idx >= n4) return;
    float4 v = *(const float4*)(src + (size_t)idx * 4);
    __half2 h0 = __floats2half2_rn(v.x, v.y);
    __half2 h1 = __floats2half2_rn(v.z, v.w);
    uint2 u;
    u.x = *(const unsigned*)&h0;
    u.y = *(const unsigned*)&h1;
    *(uint2*)(dst + (size_t)idx * 4) = u;
}

// ---------------------------------------------------------------------------
// mma.sync GEMM: C[m,n] = sum_k A[m,k]*B[n,k], K=512.
// A: Mx512 fp16 row-major; B: Nx512 fp16 row-major (TN -> mma row.col).
// MODE 0: A=g_x16,  B=g_wqkv16,  C=g_qkv16 (fp16, ldc 1536), no bias
// MODE 1: A=g_att16, B=g_wproj16, C=d_out fp32 (ldc 512), + bias, + roll(+32)
// CTA 128x128, 4 warps (2M x 2N), warp tile 64x64, BK=64, XOR-swizzled rows,
// 3-stage cp.async ring. Dynamic smem 3*256*128 = 98304 B; 2 CTAs/SM.
// ---------------------------------------------------------------------------
template <int MODE>
__global__ __launch_bounds__(128, 2) void gemm_mma(const __half* __restrict__ Aglob,
                                                   const __half* __restrict__ Bglob,
                                                   const float* __restrict__ bias,
                                                   float* __restrict__ Cout)
{
    constexpr int ASTG = 128 * 128; // bytes per A stage
    constexpr int BSTG = 128 * 128; // bytes per B stage
    extern __shared__ __align__(16) uint8_t smem_raw[];
    const uint32_t sbase = (uint32_t)__cvta_generic_to_shared(smem_raw);

    const int tid = threadIdx.x;
    const int wid = tid >> 5;
    const int lane = tid & 31;
    const int warpM = wid & 1;  // 0..1 -> 64-row slab
    const int warpN = wid >> 1; // 0..1 -> 64-col slab
    const int m0 = blockIdx.y * 128;
    const int n0 = blockIdx.x * 128;

    float acc[4][8][4];
#pragma unroll
    for (int i = 0; i < 4; ++i)
#pragma unroll
        for (int j = 0; j < 8; ++j)
#pragma unroll
            for (int r = 0; r < 4; ++r) acc[i][j][r] = 0.f;

    // ldmatrix per-lane geometry
    const int amat = lane >> 3;
    const int amrow = lane & 7;
    const int rA_loc = (amat & 1) * 8 + amrow; // row within 16-row frag
    const int chA = amat >> 1;                 // k-chunk selector (0/1)
    const int nB_loc = (lane >> 4) * 8 + (lane & 7); // row within n16 pair
    const int chB = (lane >> 3) & 1;                 // k-chunk selector

    // cp.async mapping: idx -> (row, 16B chunk); swizzle chunk ^= row&7
    auto load_stage = [&](int s, int kt) {
        const int k0 = kt * 64; // halves
        const uint32_t aB = sbase + s * ASTG;
        const uint32_t bB = sbase + 3 * ASTG + s * BSTG;
#pragma unroll
        for (int it = 0; it < 8; ++it) { // A: 128 rows x 8 chunks = 1024
            int idx = it * 128 + tid;
            int r = idx >> 3, ch = idx & 7;
            cp16(aB + r * 128 + ((ch ^ (r & 7)) << 4),
                 Aglob + (size_t)(m0 + r) * 512 + k0 + ch * 8);
        }
#pragma unroll
        for (int it = 0; it < 8; ++it) { // B: 128 rows x 8 chunks = 1024
            int idx = it * 128 + tid;
            int r = idx >> 3, ch = idx & 7;
            cp16(bB + r * 128 + ((ch ^ (r & 7)) << 4),
                 Bglob + (size_t)(n0 + r) * 512 + k0 + ch * 8);
        }
    };

    load_stage(0, 0);
    cp_commit();
    load_stage(1, 1);
    cp_commit();

    for (int kt = 0; kt < 8; ++kt) {
        cp_wait1();
        __syncthreads();

        if (kt + 2 < 8) load_stage((kt + 2) % 3, kt + 2);
        cp_commit();

        const int s = kt % 3;
        const uint32_t aB = sbase + s * ASTG;
        const uint32_t bB = sbase + 3 * ASTG + s * BSTG;

#pragma unroll
        for (int kc = 0; kc < 4; ++kc) { // 4 x k16 within BK=64
            uint32_t a[4][4];
#pragma unroll
            for (int i = 0; i < 4; ++i) {
                int r = warpM * 64 + i * 16 + rA_loc;
                uint32_t addr = aB + r * 128 + ((((kc << 1) + chA) ^ (r & 7)) << 4);
                LDSM_X4(a[i][0], a[i][1], a[i][2], a[i][3], addr);
            }
#pragma unroll
            for (int j2 = 0; j2 < 4; ++j2) { // n16 pair -> two n8 frags
                uint32_t b0, b1, b2, b3;
                int n = warpN * 64 + j2 * 16 + nB_loc;
                uint32_t addr = bB + n * 128 + ((((kc << 1) + chB) ^ (n & 7)) << 4);
                LDSM_X4(b0, b1, b2, b3, addr);
#pragma unroll
                for (int i = 0; i < 4; ++i) {
                    mma16816(acc[i][j2 * 2 + 0], a[i], b0, b1);
                    mma16816(acc[i][j2 * 2 + 1], a[i], b2, b3);
                }
            }
        }
    }

    // ---- epilogue (c0,c1 -> row lane/4, cols 2*(lane%4); c2,c3 -> row+8) ----
    const int trow = lane >> 2;
    const int tcol = (lane & 3) * 2;

    if (MODE == 0) {
#pragma unroll
        for (int i = 0; i < 4; ++i) {
            int r0 = m0 + warpM * 64 + i * 16 + trow;
            __half* p0 = g_qkv16 + (size_t)r0 * 1536 + n0 + warpN * 64 + tcol;
            __half* p1 = p0 + 8 * 1536;
#pragma unroll
            for (int j = 0; j < 8; ++j) {
                __half2 h0 = __floats2half2_rn(acc[i][j][0], acc[i][j][1]);
                __half2 h1 = __floats2half2_rn(acc[i][j][2], acc[i][j][3]);
                *(__half2*)(p0 + j * 8) = h0;
                *(__half2*)(p1 + j * 8) = h1;
            }
        }
    } else {
        const int col = n0 + warpN * 64 + tcol;
#pragma unroll
        for (int i = 0; i < 4; ++i) {
            int m = m0 + warpM * 64 + i * 16 + trow;
            int r = (m & 4095) + 32;
            if (r >= 4096) r -= 4096;
            int mo0 = (m & ~4095) | r;
            int r2 = ((m + 8) & 4095) + 32;
            if (r2 >= 4096) r2 -= 4096;
            int mo1 = ((m + 8) & ~4095) | r2;
            float* p0 = Cout + (size_t)mo0 * 512 + col;
            float* p1 = Cout + (size_t)mo1 * 512 + col;
#pragma unroll
            for (int j = 0; j < 8; ++j) {
                float2 bv = *(const float2*)(bias + col + j * 8);
                float2 v0 = {acc[i][j][0] + bv.x, acc[i][j][1] + bv.y};
                float2 v1 = {acc[i][j][2] + bv.x, acc[i][j][3] + bv.y};
                *(float2*)(p0 + j * 8) = v0;
                *(float2*)(p1 + j * 8) = v1;
            }
        }
    }
}

// ---------------------------------------------------------------------------
// Per-token 8x8 head-mixing attention + output scramble (fp32 math).
// K/V staged fp16 in smem, converted on use.
//   S[h,g] = 0.125 * q[h]·k[g];  P = softmax_g(S);  o[h] = P·v
//   g_att16[b, wi*64 + h*8 + w/8, (w%8)*64 + d] = o[h,d]
// ---------------------------------------------------------------------------
__global__ __launch_bounds__(128) void attn_kernel()
{
    __shared__ __half kv[16][1040]; // [token][ k(512) | v(512) ] fp16, padded

    const int tid = threadIdx.x;
    const int tok0 = blockIdx.x * 16;

    for (int i = tid; i < 16 * 128; i += 128) {
        int t = i >> 7;
        int off = i & 127;
        uint4 u = *(const uint4*)(g_qkv16 + (size_t)(tok0 + t) * 1536 + 512 + off * 8);
        *(uint4*)(&kv[t][off * 8]) = u;
    }
    __syncthreads();

    const int lt = tid >> 3;
    const int h = tid & 7;
    const int tok = tok0 + lt;

    const __half* qp = g_qkv16 + (size_t)tok * 1536 + h * 64;

    float S[8];
#pragma unroll
    for (int g = 0; g < 8; g++) S[g] = 0.f;

#pragma unroll
    for (int d0 = 0; d0 < 64; d0 += 8) {
        uint4 u = *(const uint4*)(qp + d0);
        const __half2* hp = (const __half2*)&u;
        float qf[8];
#pragma unroll
        for (int j = 0; j < 4; ++j) {
            float2 f = __half22float2(hp[j]);
            qf[j * 2 + 0] = f.x;
            qf[j * 2 + 1] = f.y;
        }
#pragma unroll
        for (int g = 0; g < 8; g++) {
            const __half2* kr = (const __half2*)&kv[lt][g * 64 + d0];
            float s = 0.f;
#pragma unroll
            for (int j = 0; j < 4; ++j) {
                float2 f = __half22float2(kr[j]);
                s += qf[j * 2] * f.x + qf[j * 2 + 1] * f.y;
            }
            S[g] += s;
        }
    }

    float mx = -INFINITY;
#pragma unroll
    for (int g = 0; g < 8; g++) {
        S[g] *= 0.125f;
        mx = fmaxf(mx, S[g]);
    }
    float sum = 0.f;
#pragma unroll
    for (int g = 0; g < 8; g++) {
        S[g] = expf(S[g] - mx);
        sum += S[g];
    }
    float inv = 1.f / sum;
#pragma unroll
    for (int g = 0; g < 8; g++) S[g] *= inv;

    const int n = tok & 4095;
    const int wi = n >> 6;
    const int w = n & 63;
    const int n2 = (wi << 6) | (h << 3) | (w >> 3);
    __half* op = g_att16 + (size_t)((tok & ~4095) | n2) * 512 + ((w & 7) << 6);

#pragma unroll
    for (int d0 = 0; d0 < 64; d0 += 4) {
        float4 o4 = {0.f, 0.f, 0.f, 0.f};
#pragma unroll
        for (int g = 0; g < 8; g++) {
            const __half2* vr = (const __half2*)&kv[lt][512 + g * 64 + d0];
            float2 f0 = __half22float2(vr[0]);
            float2 f1 = __half22float2(vr[1]);
            o4.x += S[g] * f0.x;
            o4.y += S[g] * f0.y;
            o4.z += S[g] * f1.x;
            o4.w += S[g] * f1.y;
        }
        __half2 h0 = __floats2half2_rn(o4.x, o4.y);
        __half2 h1 = __floats2half2_rn(o4.z, o4.w);
        uint2 u;
        u.x = *(const unsigned*)&h0;
        u.y = *(const unsigned*)&h1;
        *(uint2*)(op + d0) = u;
    }
}

// ---------------------------------------------------------------------------
extern "C" void kernel_launch(void* const* d_in, const int* in_sizes, int n_in,
                              void* d_out, int out_size)
{
    const float* x = (const float*)d_in[0];
    const float* w_qkv = (const float*)d_in[1];
    const float* w_proj = (const float*)d_in[2];
    const float* b_proj = (const float*)d_in[3];
    float* out = (float*)d_out;
    (void)in_sizes; (void)n_in; (void)out_size;

    __half* wq16;
    __half* wp16;
    __half* x16;
    __half* a16;
    cudaGetSymbolAddress((void**)&wq16, g_wqkv16);
    cudaGetSymbolAddress((void**)&wp16, g_wproj16);
    cudaGetSymbolAddress((void**)&x16, g_x16);
    cudaGetSymbolAddress((void**)&a16, g_att16);

    constexpr int GEMM_SMEM = 3 * 256 * 128; // 98304 B -> 2 CTAs/SM
    cudaFuncSetAttribute(gemm_mma<0>, cudaFuncAttributeMaxDynamicSharedMemorySize, GEMM_SMEM);
    cudaFuncSetAttribute(gemm_mma<1>, cudaFuncAttributeMaxDynamicSharedMemorySize, GEMM_SMEM);

    // 1) fp16 conversions (roll(-32) fused into x)
    conv_x_kernel<<<(NTOK * 512 / 4) / 256, 256>>>(x);
    conv_w_kernel<<<(1536 * 512 / 4 + 255) / 256, 256>>>(w_qkv, wq16, 1536 * 512 / 4);
    conv_w_kernel<<<(512 * 512 / 4 + 255) / 256, 256>>>(w_proj, wp16, 512 * 512 / 4);

    // 2) QKV GEMM (mma.sync + ldmatrix, 2 CTAs/SM) -> g_qkv16 fp16
    gemm_mma<0><<<dim3(1536 / 128, NTOK / 128), 128, GEMM_SMEM>>>(x16, wq16, nullptr, nullptr);

    // 3) per-token 8x8 head attention + scramble -> g_att16
    attn_kernel<<<NTOK / 16, 128>>>();

    // 4) proj GEMM + bias + roll(+32) -> d_out
    gemm_mma<1><<<dim3(512 / 128, NTOK / 128), 128, GEMM_SMEM>>>(a16, wp16, b_proj, out);
}

// round 17
// speedup vs baseline: 1.3800x; 1.0088x over previous
#include <cuda_runtime.h>
#include <cuda_fp16.h>
#include <cstdint>
#include <math.h>

// x: (8,4096,512) f32 ; w_qkv: (1536,512) ; w_proj: (512,512) ; b_proj: (512)
// H=8, head_dim=64, W=64, SHIFT=32, SCALE=0.125
#define NTOK (8 * 4096)

// -------- scratch (__device__ globals; no allocation allowed) --------
__device__ __half g_x16[(size_t)NTOK * 512];     // rolled(-32) x, fp16
__device__ __half g_qkv16[(size_t)NTOK * 1536];  // q|k|v per token, fp16
__device__ __half g_att16[(size_t)NTOK * 512];   // scrambled attention out, fp16
__device__ __half g_wqkv16[1536 * 512];
__device__ __half g_wproj16[512 * 512];

// ---------------------------------------------------------------------------
// PTX helpers
// ---------------------------------------------------------------------------
__device__ __forceinline__ void cp16(uint32_t smem_addr, const void* gmem_src) {
    asm volatile("cp.async.cg.shared.global [%0], [%1], 16;" :: "r"(smem_addr), "l"(gmem_src));
}
__device__ __forceinline__ void cp_commit() { asm volatile("cp.async.commit_group;"); }
__device__ __forceinline__ void cp_wait1() { asm volatile("cp.async.wait_group 1;"); }

#define LDSM_X4(R0, R1, R2, R3, ADDR)                                             \
    asm volatile("ldmatrix.sync.aligned.m8n8.x4.shared.b16 {%0,%1,%2,%3}, [%4];"  \
                 : "=r"(R0), "=r"(R1), "=r"(R2), "=r"(R3) : "r"(ADDR))

__device__ __forceinline__ void mma16816(float* c, const uint32_t* a, uint32_t b0, uint32_t b1) {
    asm volatile(
        "mma.sync.aligned.m16n8k16.row.col.f32.f16.f16.f32 "
        "{%0,%1,%2,%3}, {%4,%5,%6,%7}, {%8,%9}, {%0,%1,%2,%3};"
        : "+f"(c[0]), "+f"(c[1]), "+f"(c[2]), "+f"(c[3])
        : "r"(a[0]), "r"(a[1]), "r"(a[2]), "r"(a[3]), "r"(b0), "r"(b1));
}

// ---------------------------------------------------------------------------
// conversion kernels (fp32 -> fp16), roll(-32) fused into x conversion
// ---------------------------------------------------------------------------
__global__ void conv_x_kernel(const float* __restrict__ x) {
    size_t idx = (size_t)blockIdx.x * 256 + threadIdx.x; // one float4 each
    int m = (int)(idx >> 7);
    int c = (int)(idx & 127) * 4;
    int msrc = (m & ~4095) | (((m & 4095) + 32) & 4095); // roll(-32)
    float4 v = *(const float4*)(x + (size_t)msrc * 512 + c);
    __half2 h0 = __floats2half2_rn(v.x, v.y);
    __half2 h1 = __floats2half2_rn(v.z, v.w);
    uint2 u;
    u.x = *(const unsigned*)&h0;
    u.y = *(const unsigned*)&h1;
    *(uint2*)(g_x16 + (size_t)m * 512 + c) = u;
}

__global__ void conv_w_kernel(const float* __restrict__ src, __half* __restrict__ dst, int n4) {
    int idx = blockIdx.x * 256 + threadIdx.x;
    if (idx >= n4) return;
    float4 v = *(const float4*)(src + (size_t)idx * 4);
    __half2 h0 = __floats2half2_rn(v.x, v.y);
    __half2 h1 = __floats2half2_rn(v.z, v.w);
    uint2 u;
    u.x = *(const unsigned*)&h0;
    u.y = *(const unsigned*)&h1;
    *(uint2*)(dst + (size_t)idx * 4) = u;
}

// ---------------------------------------------------------------------------
// mma.sync GEMM: C[m,n] = sum_k A[m,k]*B[n,k], K=512.
// A: Mx512 fp16 row-major; B: Nx512 fp16 row-major (TN -> mma row.col).
// MODE 0: A=g_x16,  B=g_wqkv16,  C=g_qkv16 (fp16, ldc 1536), no bias
// MODE 1: A=g_att16, B=g_wproj16, C=d_out fp32 (ldc 512), + bias, + roll(+32)
// CTA 128x128, 4 warps (2M x 2N), warp tile 64x64, BK=64, XOR-swizzled rows,
// 3-stage cp.async ring, 2 CTAs/SM. Mainloop keeps the CORRECT ordering
// (wait -> syncthreads -> issue next loads -> compute): the barrier AFTER the
// wait is what publishes other threads' cp.async data to this warp.
// Within each kc, all 8 ldmatrix are hoisted ahead of the 16 MMAs.
// ---------------------------------------------------------------------------
template <int MODE>
__global__ __launch_bounds__(128, 2) void gemm_mma(const __half* __restrict__ Aglob,
                                                   const __half* __restrict__ Bglob,
                                                   const float* __restrict__ bias,
                                                   float* __restrict__ Cout)
{
    constexpr int ASTG = 128 * 128; // bytes per A stage
    constexpr int BSTG = 128 * 128; // bytes per B stage
    extern __shared__ __align__(16) uint8_t smem_raw[];
    const uint32_t sbase = (uint32_t)__cvta_generic_to_shared(smem_raw);

    const int tid = threadIdx.x;
    const int wid = tid >> 5;
    const int lane = tid & 31;
    const int warpM = wid & 1;  // 0..1 -> 64-row slab
    const int warpN = wid >> 1; // 0..1 -> 64-col slab
    const int m0 = blockIdx.y * 128;
    const int n0 = blockIdx.x * 128;

    float acc[4][8][4];
#pragma unroll
    for (int i = 0; i < 4; ++i)
#pragma unroll
        for (int j = 0; j < 8; ++j)
#pragma unroll
            for (int r = 0; r < 4; ++r) acc[i][j][r] = 0.f;

    // ldmatrix per-lane geometry
    const int amat = lane >> 3;
    const int amrow = lane & 7;
    const int rA_loc = (amat & 1) * 8 + amrow; // row within 16-row frag
    const int chA = amat >> 1;                 // k-chunk selector (0/1)
    const int nB_loc = (lane >> 4) * 8 + (lane & 7); // row within n16 pair
    const int chB = (lane >> 3) & 1;                 // k-chunk selector

    // cp.async mapping: idx -> (row, 16B chunk); swizzle chunk ^= row&7
    auto load_stage = [&](int s, int kt) {
        const int k0 = kt * 64; // halves
        const uint32_t aB = sbase + s * ASTG;
        const uint32_t bB = sbase + 3 * ASTG + s * BSTG;
#pragma unroll
        for (int it = 0; it < 8; ++it) { // A: 128 rows x 8 chunks = 1024
            int idx = it * 128 + tid;
            int r = idx >> 3, ch = idx & 7;
            cp16(aB + r * 128 + ((ch ^ (r & 7)) << 4),
                 Aglob + (size_t)(m0 + r) * 512 + k0 + ch * 8);
        }
#pragma unroll
        for (int it = 0; it < 8; ++it) { // B: 128 rows x 8 chunks = 1024
            int idx = it * 128 + tid;
            int r = idx >> 3, ch = idx & 7;
            cp16(bB + r * 128 + ((ch ^ (r & 7)) << 4),
                 Bglob + (size_t)(n0 + r) * 512 + k0 + ch * 8);
        }
    };

    load_stage(0, 0);
    cp_commit();
    load_stage(1, 1);
    cp_commit();

    for (int kt = 0; kt < 8; ++kt) {
        cp_wait1();      // stage kt's group complete (own thread)
        __syncthreads(); // publish ALL threads' copies; also frees slot (kt+2)%3

        if (kt + 2 < 8) load_stage((kt + 2) % 3, kt + 2);
        cp_commit();

        const int s = kt % 3;
        const uint32_t aB = sbase + s * ASTG;
        const uint32_t bB = sbase + 3 * ASTG + s * BSTG;

#pragma unroll
        for (int kc = 0; kc < 4; ++kc) { // 4 x k16 within BK=64
            // hoist ALL fragment loads: 8 ldsm pipeline back-to-back,
            // one exposed latency window per kc instead of four
            uint32_t a[4][4];
            uint32_t b[4][4];
#pragma unroll
            for (int i = 0; i < 4; ++i) {
                int r = warpM * 64 + i * 16 + rA_loc;
                uint32_t addr = aB + r * 128 + ((((kc << 1) + chA) ^ (r & 7)) << 4);
                LDSM_X4(a[i][0], a[i][1], a[i][2], a[i][3], addr);
            }
#pragma unroll
            for (int j2 = 0; j2 < 4; ++j2) {
                int n = warpN * 64 + j2 * 16 + nB_loc;
                uint32_t addr = bB + n * 128 + ((((kc << 1) + chB) ^ (n & 7)) << 4);
                LDSM_X4(b[j2][0], b[j2][1], b[j2][2], b[j2][3], addr);
            }
#pragma unroll
            for (int j2 = 0; j2 < 4; ++j2) {
#pragma unroll
                for (int i = 0; i < 4; ++i) {
                    mma16816(acc[i][j2 * 2 + 0], a[i], b[j2][0], b[j2][1]);
                    mma16816(acc[i][j2 * 2 + 1], a[i], b[j2][2], b[j2][3]);
                }
            }
        }
    }

    // ---- epilogue (c0,c1 -> row lane/4, cols 2*(lane%4); c2,c3 -> row+8) ----
    const int trow = lane >> 2;
    const int tcol = (lane & 3) * 2;

    if (MODE == 0) {
#pragma unroll
        for (int i = 0; i < 4; ++i) {
            int r0 = m0 + warpM * 64 + i * 16 + trow;
            __half* p0 = g_qkv16 + (size_t)r0 * 1536 + n0 + warpN * 64 + tcol;
            __half* p1 = p0 + 8 * 1536;
#pragma unroll
            for (int j = 0; j < 8; ++j) {
                __half2 h0 = __floats2half2_rn(acc[i][j][0], acc[i][j][1]);
                __half2 h1 = __floats2half2_rn(acc[i][j][2], acc[i][j][3]);
                *(__half2*)(p0 + j * 8) = h0;
                *(__half2*)(p1 + j * 8) = h1;
            }
        }
    } else {
        const int col = n0 + warpN * 64 + tcol;
#pragma unroll
        for (int i = 0; i < 4; ++i) {
            int m = m0 + warpM * 64 + i * 16 + trow;
            int r = (m & 4095) + 32;
            if (r >= 4096) r -= 4096;
            int mo0 = (m & ~4095) | r;
            int r2 = ((m + 8) & 4095) + 32;
            if (r2 >= 4096) r2 -= 4096;
            int mo1 = ((m + 8) & ~4095) | r2;
            float* p0 = Cout + (size_t)mo0 * 512 + col;
            float* p1 = Cout + (size_t)mo1 * 512 + col;
#pragma unroll
            for (int j = 0; j < 8; ++j) {
                float2 bv = *(const float2*)(bias + col + j * 8);
                float2 v0 = {acc[i][j][0] + bv.x, acc[i][j][1] + bv.y};
                float2 v1 = {acc[i][j][2] + bv.x, acc[i][j][3] + bv.y};
                *(float2*)(p0 + j * 8) = v0;
                *(float2*)(p1 + j * 8) = v1;
            }
        }
    }
}

// ---------------------------------------------------------------------------
// Per-token 8x8 head-mixing attention + output scramble (fp32 math).
// K/V staged fp16 in smem, converted on use.
//   S[h,g] = 0.125 * q[h]·k[g];  P = softmax_g(S);  o[h] = P·v
//   g_att16[b, wi*64 + h*8 + w/8, (w%8)*64 + d] = o[h,d]
// ---------------------------------------------------------------------------
__global__ __launch_bounds__(128) void attn_kernel()
{
    __shared__ __half kv[16][1040]; // [token][ k(512) | v(512) ] fp16, padded

    const int tid = threadIdx.x;
    const int tok0 = blockIdx.x * 16;

    for (int i = tid; i < 16 * 128; i += 128) {
        int t = i >> 7;
        int off = i & 127;
        uint4 u = *(const uint4*)(g_qkv16 + (size_t)(tok0 + t) * 1536 + 512 + off * 8);
        *(uint4*)(&kv[t][off * 8]) = u;
    }
    __syncthreads();

    const int lt = tid >> 3;
    const int h = tid & 7;
    const int tok = tok0 + lt;

    const __half* qp = g_qkv16 + (size_t)tok * 1536 + h * 64;

    float S[8];
#pragma unroll
    for (int g = 0; g < 8; g++) S[g] = 0.f;

#pragma unroll
    for (int d0 = 0; d0 < 64; d0 += 8) {
        uint4 u = *(const uint4*)(qp + d0);
        const __half2* hp = (const __half2*)&u;
        float qf[8];
#pragma unroll
        for (int j = 0; j < 4; ++j) {
            float2 f = __half22float2(hp[j]);
            qf[j * 2 + 0] = f.x;
            qf[j * 2 + 1] = f.y;
        }
#pragma unroll
        for (int g = 0; g < 8; g++) {
            const __half2* kr = (const __half2*)&kv[lt][g * 64 + d0];
            float s = 0.f;
#pragma unroll
            for (int j = 0; j < 4; ++j) {
                float2 f = __half22float2(kr[j]);
                s += qf[j * 2] * f.x + qf[j * 2 + 1] * f.y;
            }
            S[g] += s;
        }
    }

    float mx = -INFINITY;
#pragma unroll
    for (int g = 0; g < 8; g++) {
        S[g] *= 0.125f;
        mx = fmaxf(mx, S[g]);
    }
    float sum = 0.f;
#pragma unroll
    for (int g = 0; g < 8; g++) {
        S[g] = expf(S[g] - mx);
        sum += S[g];
    }
    float inv = 1.f / sum;
#pragma unroll
    for (int g = 0; g < 8; g++) S[g] *= inv;

    const int n = tok & 4095;
    const int wi = n >> 6;
    const int w = n & 63;
    const int n2 = (wi << 6) | (h << 3) | (w >> 3);
    __half* op = g_att16 + (size_t)((tok & ~4095) | n2) * 512 + ((w & 7) << 6);

#pragma unroll
    for (int d0 = 0; d0 < 64; d0 += 4) {
        float4 o4 = {0.f, 0.f, 0.f, 0.f};
#pragma unroll
        for (int g = 0; g < 8; g++) {
            const __half2* vr = (const __half2*)&kv[lt][512 + g * 64 + d0];
            float2 f0 = __half22float2(vr[0]);
            float2 f1 = __half22float2(vr[1]);
            o4.x += S[g] * f0.x;
            o4.y += S[g] * f0.y;
            o4.z += S[g] * f1.x;
            o4.w += S[g] * f1.y;
        }
        __half2 h0 = __floats2half2_rn(o4.x, o4.y);
        __half2 h1 = __floats2half2_rn(o4.z, o4.w);
        uint2 u;
        u.x = *(const unsigned*)&h0;
        u.y = *(const unsigned*)&h1;
        *(uint2*)(op + d0) = u;
    }
}

// ---------------------------------------------------------------------------
extern "C" void kernel_launch(void* const* d_in, const int* in_sizes, int n_in,
                              void* d_out, int out_size)
{
    const float* x = (const float*)d_in[0];
    const float* w_qkv = (const float*)d_in[1];
    const float* w_proj = (const float*)d_in[2];
    const float* b_proj = (const float*)d_in[3];
    float* out = (float*)d_out;
    (void)in_sizes; (void)n_in; (void)out_size;

    __half* wq16;
    __half* wp16;
    __half* x16;
    __half* a16;
    cudaGetSymbolAddress((void**)&wq16, g_wqkv16);
    cudaGetSymbolAddress((void**)&wp16, g_wproj16);
    cudaGetSymbolAddress((void**)&x16, g_x16);
    cudaGetSymbolAddress((void**)&a16, g_att16);

    constexpr int GEMM_SMEM = 3 * 256 * 128; // 98304 B -> 2 CTAs/SM
    cudaFuncSetAttribute(gemm_mma<0>, cudaFuncAttributeMaxDynamicSharedMemorySize, GEMM_SMEM);
    cudaFuncSetAttribute(gemm_mma<1>, cudaFuncAttributeMaxDynamicSharedMemorySize, GEMM_SMEM);

    // 1) fp16 conversions (roll(-32) fused into x)
    conv_x_kernel<<<(NTOK * 512 / 4) / 256, 256>>>(x);
    conv_w_kernel<<<(1536 * 512 / 4 + 255) / 256, 256>>>(w_qkv, wq16, 1536 * 512 / 4);
    conv_w_kernel<<<(512 * 512 / 4 + 255) / 256, 256>>>(w_proj, wp16, 512 * 512 / 4);

    // 2) QKV GEMM (mma.sync + ldmatrix, 2 CTAs/SM) -> g_qkv16 fp16
    gemm_mma<0><<<dim3(1536 / 128, NTOK / 128), 128, GEMM_SMEM>>>(x16, wq16, nullptr, nullptr);

    // 3) per-token 8x8 head attention + scramble -> g_att16
    attn_kernel<<<NTOK / 16, 128>>>();

    // 4) proj GEMM + bias + roll(+32) -> d_out
    gemm_mma<1><<<dim3(512 / 128, NTOK / 128), 128, GEMM_SMEM>>>(a16, wp16, b_proj, out);
}